// round 8
// baseline (speedup 1.0000x reference)
#include <cuda_runtime.h>
#include <math.h>

// ---------------------------------------------------------------------------
// HistogramLoss on GB300 — d-grouped (float4) single-pass histogram KDE.
//
// feature: [1, 64, 128, 128] fp32 ; label: [1, 1, 512, 512] int32 ; out: scalar
//
// Per class c, dim d:
//   miu = Σ w x / n,  var = Σ w x²/n - miu² + 1e-10
//   S[k] = Σ_q w[c,q] exp(-12.5 ((miu + k·std - x_q)/std)²),  k = -3..3
//   hist = S/ΣS, targ = const normalized gaussian, loss = mean smooth_l1
//
// Pipeline:
//   k_init     : zero counters, build target
//   k_build_tr : blocks 0..63   : 4x4 label counts -> per-class packed lists
//                blocks 64..1087: transpose feature [d][q] -> [q][d]
//   k_fused    : one block per (dgroup of 4, c): single pass over compact list
//                does register stats + 4 weighted x-histograms (2560 bins,
//                δ=1/256 over [-5,5)); then exact-stat params; KDE via
//                on-the-fly gaussian recurrence; smooth-l1 vs target.
//   k_final    : one warp per class, scalar reduce
// ---------------------------------------------------------------------------

#define NUM_C  19
#define PC     16384            // 128*128 coarse pixels
#define DD     64
#define GD     4                // d-values per fused block
#define NGRP   (DD / GD)        // 16
#define NBX    2560             // x-histogram bins over [-5, 5), delta = 1/256
#define HWF    1.30f            // gaussian half-window in std units

__device__ unsigned int g_list[NUM_C * PC];   // packed (q<<5)|w
__device__ int    g_cnt[NUM_C];               // entries per class
__device__ int    g_n[NUM_C];                 // per-class total fine-pixel counts
__device__ float  g_partial[NUM_C * DD];      // per-(c,d) smooth-l1 sum over 7 bins
__device__ float  g_targ[7];                  // normalized target histogram
__device__ float4 g_xt[PC * NGRP];            // transposed feature: [q][dgrp] float4

// ---------------------------------------------------------------- init ----
__global__ void k_init() {
    int t = threadIdx.x;
    if (t < NUM_C) { g_cnt[t] = 0; g_n[t] = 0; }
    if (t == 0) {
        float tv[7]; float s = 0.f;
        #pragma unroll
        for (int k = 0; k < 7; k++) { float kk = (float)(k - 3); tv[k] = expf(-0.5f * kk * kk); s += tv[k]; }
        #pragma unroll
        for (int k = 0; k < 7; k++) g_targ[k] = tv[k] / s;
    }
}

// ----------------------------------------------------- build + transpose ----
// blocks 0..63: per-pixel 4x4 label counts -> warp-aggregated list append.
// blocks 64..1087: 32x32 tiled transpose of feature into g_xt.
__global__ __launch_bounds__(256) void k_build_tr(const int* __restrict__ label,
                                                  const float* __restrict__ feat) {
    __shared__ float tile[32][33];
    int t = threadIdx.x;
    int lane = t & 31;

    if (blockIdx.x < 64) {
        int q = blockIdx.x * 256 + t;           // 64 blocks * 256 = 16384
        int y = q >> 7, x = q & 127;
        const int4* lp = (const int4*)label;    // 512 ints per fine row = 128 int4
        int base = y * 512 + x;                 // int4 index of fine row 4y, col 4x

        int w[NUM_C];
        #pragma unroll
        for (int c = 0; c < NUM_C; c++) w[c] = 0;

        #pragma unroll
        for (int r = 0; r < 4; r++) {
            int4 v = lp[base + r * 128];
            #pragma unroll
            for (int c = 0; c < NUM_C; c++)
                w[c] += (v.x == c) + (v.y == c) + (v.z == c) + (v.w == c);
        }

        unsigned lmask = (1u << lane) - 1u;
        #pragma unroll
        for (int c = 0; c < NUM_C; c++) {
            bool p = (w[c] != 0);
            unsigned bal = __ballot_sync(0xffffffffu, p);
            int cnt = __popc(bal);
            int tot = __reduce_add_sync(0xffffffffu, w[c]);
            if (cnt) {                                    // warp-uniform
                int seg;
                if (lane == 0) {
                    seg = atomicAdd(&g_cnt[c], cnt);
                    atomicAdd(&g_n[c], tot);
                }
                seg = __shfl_sync(0xffffffffu, seg, 0);
                if (p) g_list[c * PC + seg + __popc(bal & lmask)] =
                           ((unsigned)q << 5) | (unsigned)w[c];
            }
        }
    } else {
        int tb = blockIdx.x - 64;               // 1024 tiles
        int q0 = (tb & 511) * 32;               // 512 q-tiles
        int d0 = (tb >> 9) * 32;                // 2 d-tiles
        int tx = lane, ty = t >> 5;             // 32 x 8
        for (int r = ty; r < 32; r += 8)
            tile[r][tx] = feat[(d0 + r) * PC + q0 + tx];
        __syncthreads();
        float* xtf = (float*)g_xt;
        for (int r = ty; r < 32; r += 8)
            xtf[(q0 + r) * DD + d0 + tx] = tile[tx][r];
    }
}

// --------------------------------------------------------------- fused ----
// One block per (dgroup, c).
__global__ __launch_bounds__(256) void k_fused() {
    int dg = blockIdx.x, c = blockIdx.y;
    int t = threadIdx.x;
    int lane = t & 31, wid = t >> 5;

    __shared__ float H[GD * NBX];          // 40 KB
    __shared__ float rs1[8][GD], rs2[8][GD];
    __shared__ float4 s_par[GD];           // (A, jb0, std_bins, halfwin_bins)
    __shared__ float S7[GD][7];

    for (int i = t; i < GD * NBX; i += 256) H[i] = 0.f;
    __syncthreads();

    int nnz = g_cnt[c];
    const unsigned int* __restrict__ list = g_list + c * PC;
    const float4* __restrict__ xt = g_xt + dg;

    // ---- single data pass: register stats + 4 weighted x-histograms ----
    float s1[GD], s2[GD];
    #pragma unroll
    for (int j = 0; j < GD; j++) { s1[j] = 0.f; s2[j] = 0.f; }

    #pragma unroll 2
    for (int i = t; i < nnz; i += 256) {
        unsigned e = list[i];
        float w = (float)(e & 31u);
        float4 xv = xt[(e >> 5) * NGRP];
        float xa[GD] = { xv.x, xv.y, xv.z, xv.w };
        #pragma unroll
        for (int j = 0; j < GD; j++) {
            float x  = xa[j];
            float wx = w * x;
            s1[j] += wx;
            s2[j] = fmaf(wx, x, s2[j]);
            float jf = fmaf(x, 256.f, 1280.f);               // (x+5)*256
            jf = fminf(fmaxf(jf, 0.f), (float)(NBX - 1));
            atomicAdd(&H[j * NBX + (int)jf], w);             // integer adds: exact
        }
    }
    #pragma unroll
    for (int j = 0; j < GD; j++) {
        #pragma unroll
        for (int o = 16; o; o >>= 1) {
            s1[j] += __shfl_down_sync(0xffffffffu, s1[j], o);
            s2[j] += __shfl_down_sync(0xffffffffu, s2[j], o);
        }
    }
    if (lane == 0) {
        #pragma unroll
        for (int j = 0; j < GD; j++) { rs1[wid][j] = s1[j]; rs2[wid][j] = s2[j]; }
    }
    __syncthreads();

    if (t < GD) {
        int j = t;
        float a = 0.f, b = 0.f;
        #pragma unroll
        for (int i = 0; i < 8; i++) { a += rs1[i][j]; b += rs2[i][j]; }
        float n   = (float)g_n[c];
        float ns  = fmaxf(n, 1.0f);
        float miu = a / ns;
        float var = b / ns - miu * miu + 1e-10f;
        var = fmaxf(var, 1e-10f);
        float std = sqrtf(var);
        s_par[j] = make_float4(12.5f / (var * 65536.0f),     // A (bin units)
                               fmaf(miu, 256.f, 1279.5f),    // jb0
                               std * 256.0f,                 // std in bins
                               HWF * std * 256.0f);          // half window
    }
    __syncthreads();

    // ---- KDE: 28 (j,k) warp-tasks over 8 warps ----
    for (int task = wid; task < GD * 7; task += 8) {
        int j = task & 3;                    // histogram row (constant per warp)
        int k = (task >> 2) - 3;
        float4 p = s_par[j];
        float A  = p.x;
        float jb = fmaf((float)k, p.z, p.y);
        float hw = p.w;
        int jlo = max(0,        (int)ceilf(jb - hw));
        int jhi = min(NBX - 1,  (int)floorf(jb + hw));
        const float* Hj = H + j * NBX;
        float acc = 0.f;
        int jj = jlo + lane;
        if (jj <= jhi) {
            float dd  = (float)jj - jb;
            float e   = __expf(-A * dd * dd);
            float r   = __expf(-A * fmaf(64.f, dd, 1024.f)); // ratio j -> j+32
            float c32 = __expf(-2048.f * A);                 // ratio update
            for (; jj <= jhi; jj += 32) {
                acc = fmaf(e, Hj[jj], acc);
                e *= r;
                r *= c32;
            }
        }
        #pragma unroll
        for (int o = 16; o; o >>= 1) acc += __shfl_down_sync(0xffffffffu, acc, o);
        if (lane == 0) S7[j][(task >> 2)] = acc;
    }
    __syncthreads();

    if (t < GD) {
        int j = t;
        float tot = 0.f;
        #pragma unroll
        for (int k = 0; k < 7; k++) tot += S7[j][k];
        float inv = 1.0f / fmaxf(tot, 1e-30f);
        float ls = 0.f;
        #pragma unroll
        for (int k = 0; k < 7; k++) {
            float dlt = S7[j][k] * inv - g_targ[k];
            float aa = fabsf(dlt);
            ls += (aa < 1.f) ? 0.5f * aa * aa : aa - 0.5f;
        }
        g_partial[c * DD + dg * GD + j] = ls;
    }
}

// --------------------------------------------------------------- final ----
// One warp per class.
__global__ void k_final(float* __restrict__ out) {
    int t = threadIdx.x;
    int lane = t & 31, c = t >> 5;            // 19 warps
    __shared__ float sl[NUM_C], sa[NUM_C];
    float s = g_partial[c * DD + lane] + g_partial[c * DD + 32 + lane];
    #pragma unroll
    for (int o = 16; o; o >>= 1) s += __shfl_down_sync(0xffffffffu, s, o);
    if (lane == 0) {
        float act = (g_n[c] >= 1000) ? 1.f : 0.f;
        sl[c] = s * (1.0f / 448.0f) * act;    // mean over 64*7 elements, masked
        sa[c] = act;
    }
    __syncthreads();
    if (t == 0) {
        float L = 0.f, A = 0.f;
        #pragma unroll
        for (int cc = 0; cc < NUM_C; cc++) { L += sl[cc]; A += sa[cc]; }
        out[0] = L / A;
    }
}

// -------------------------------------------------------------- launch ----
extern "C" void kernel_launch(void* const* d_in, const int* in_sizes, int n_in,
                              void* d_out, int out_size) {
    const float* feat  = (const float*)d_in[0];
    const int*   label = (const int*)d_in[1];
    // robustness: identify inputs by element count (feature=1048576, label=262144)
    if (n_in >= 2 && in_sizes[0] == 262144) {
        feat  = (const float*)d_in[1];
        label = (const int*)d_in[0];
    }

    k_init<<<1, 32>>>();
    k_build_tr<<<64 + 1024, 256>>>(label, feat);
    dim3 g(NGRP, NUM_C);
    k_fused<<<g, 256>>>();
    k_final<<<1, NUM_C * 32>>>((float*)d_out);
}

// round 11
// speedup vs baseline: 1.2684x; 1.2684x over previous
#include <cuda_runtime.h>
#include <math.h>

// ---------------------------------------------------------------------------
// HistogramLoss on GB300 — single-pass x-histogram KDE, 3-launch pipeline.
//
// feature: [1, 64, 128, 128] fp32 ; label: [1, 1, 512, 512] int32 ; out: scalar
//
// Per class c, dim d:
//   miu = Σ w x / n,  var = Σ w x²/n - miu² + 1e-10
//   S[k] = Σ_q w[c,q] exp(-12.5 ((miu + k·std - x_q)/std)²),  k = -3..3
//   hist = S/ΣS, targ = const normalized gaussian, loss = mean smooth_l1
//
// Pipeline (counters statically zero; k_final re-zeros them for graph replay):
//   k_build : per-pixel 4x4 label counts -> per-class packed lists via
//             warp-aggregated atomic reservation (order-free; sums exact)
//   k_fused : per (c,d): one pass -> register stats + weighted x-histogram
//             (3072 bins, δ=1/256 over [-6,6)); KDE via on-the-fly gaussian
//             recurrence; smooth-l1 vs hardcoded target
//   k_final : one warp per class, scalar reduce; re-zero counters
// ---------------------------------------------------------------------------

#define NUM_C  19
#define PC     16384            // 128*128 coarse pixels
#define DD     64
#define NBX    3072             // x-histogram bins over [-6, 6), delta = 1/256
#define HWF    1.30f            // gaussian half-window in std units

__device__ unsigned int g_list[NUM_C * PC];   // packed (q<<5)|w
__device__ int    g_cnt[NUM_C];               // entries per class  (zero-init)
__device__ int    g_n[NUM_C];                 // class totals       (zero-init)
__device__ float  g_partial[NUM_C * DD];      // per-(c,d) smooth-l1 sum

// target histogram exp(-0.5 k^2)/sum, k=-3..3 (exact constants)
__constant__ float c_targ[7] = {
    0.00443305f, 0.05400557f, 0.24203623f, 0.39905027f,
    0.24203623f, 0.05400557f, 0.00443305f };

// --------------------------------------------------------------- build ----
// One thread per coarse pixel: count labels in its 4x4 fine block, then
// warp-aggregated reservation into per-class compact lists.
__global__ __launch_bounds__(256) void k_build(const int* __restrict__ label) {
    int t = threadIdx.x;
    int lane = t & 31;
    int q = blockIdx.x * 256 + t;           // 64 blocks * 256 = 16384
    int y = q >> 7, x = q & 127;
    const int4* lp = (const int4*)label;    // 512 ints per fine row = 128 int4
    int base = y * 512 + x;                 // int4 index of fine row 4y, col 4x

    int w[NUM_C];
    #pragma unroll
    for (int c = 0; c < NUM_C; c++) w[c] = 0;

    #pragma unroll
    for (int r = 0; r < 4; r++) {
        int4 v = lp[base + r * 128];
        #pragma unroll
        for (int c = 0; c < NUM_C; c++)
            w[c] += (v.x == c) + (v.y == c) + (v.z == c) + (v.w == c);
    }

    unsigned lmask = (1u << lane) - 1u;
    #pragma unroll
    for (int c = 0; c < NUM_C; c++) {
        bool p = (w[c] != 0);
        unsigned bal = __ballot_sync(0xffffffffu, p);
        int cnt = __popc(bal);
        int tot = __reduce_add_sync(0xffffffffu, w[c]);
        if (cnt) {                                    // warp-uniform
            int seg;
            if (lane == 0) {
                seg = atomicAdd(&g_cnt[c], cnt);
                atomicAdd(&g_n[c], tot);
            }
            seg = __shfl_sync(0xffffffffu, seg, 0);
            if (p) g_list[c * PC + seg + __popc(bal & lmask)] =
                       ((unsigned)q << 5) | (unsigned)w[c];
        }
    }
}

// --------------------------------------------------------------- fused ----
// One block per (d, c): single pass over the compact list accumulates exact
// register stats AND the weighted x-histogram; then KDE + smooth-l1.
__global__ __launch_bounds__(256) void k_fused(const float* __restrict__ feat) {
    int d = blockIdx.x, c = blockIdx.y;
    int t = threadIdx.x;
    int lane = t & 31, wid = t >> 5;

    __shared__ float H[NBX];
    __shared__ float S7[7];
    __shared__ float r1[8], r2[8];
    __shared__ float s_par[4];     // A, jb0, std_bins, halfwin_bins

    for (int i = t; i < NBX; i += 256) H[i] = 0.f;
    __syncthreads();

    int nnz = g_cnt[c];
    const unsigned int* __restrict__ list = g_list + c * PC;
    const float* __restrict__ xrow = feat + d * PC;

    // ---- single data pass: exact stats + weighted x-histogram ----
    float s1 = 0.f, s2 = 0.f;
    #pragma unroll 4
    for (int i = t; i < nnz; i += 256) {
        unsigned e = list[i];
        float w  = (float)(e & 31u);
        float x  = xrow[e >> 5];
        float wx = w * x;
        s1 += wx;
        s2 = fmaf(wx, x, s2);
        float jf = fmaf(x, 256.f, 1536.f);           // (x+6)*256
        jf = fminf(fmaxf(jf, 0.f), (float)(NBX - 1));
        atomicAdd(&H[(int)jf], w);                   // integer adds: exact
    }
    #pragma unroll
    for (int o = 16; o; o >>= 1) {
        s1 += __shfl_down_sync(0xffffffffu, s1, o);
        s2 += __shfl_down_sync(0xffffffffu, s2, o);
    }
    if (lane == 0) { r1[wid] = s1; r2[wid] = s2; }
    __syncthreads();
    if (t == 0) {
        float a = 0.f, b = 0.f;
        #pragma unroll
        for (int i = 0; i < 8; i++) { a += r1[i]; b += r2[i]; }
        float n   = (float)g_n[c];
        float ns  = fmaxf(n, 1.0f);
        float miu = a / ns;
        float var = b / ns - miu * miu + 1e-10f;
        var = fmaxf(var, 1e-10f);
        float std = sqrtf(var);
        s_par[0] = 12.5f / (var * 65536.0f);          // A (bin units)
        s_par[1] = fmaf(miu, 256.f, 1535.5f);         // jb0: bin coord of miu
        s_par[2] = std * 256.0f;                      // std in bins
        s_par[3] = HWF * std * 256.0f;                // half window in bins
    }
    __syncthreads();

    // ---- 7-bin KDE: warp wid handles k = wid-3 ----
    if (wid < 7) {
        float A  = s_par[0];
        float jb = fmaf((float)(wid - 3), s_par[2], s_par[1]);
        float hw = s_par[3];
        int jlo = max(0,        (int)ceilf(jb - hw));
        int jhi = min(NBX - 1,  (int)floorf(jb + hw));
        float acc = 0.f;
        int j = jlo + lane;
        if (j <= jhi) {
            float dd  = (float)j - jb;
            float e   = __expf(-A * dd * dd);
            float r   = __expf(-A * fmaf(64.f, dd, 1024.f));   // ratio j -> j+32
            float c32 = __expf(-2048.f * A);                   // ratio update
            for (; j <= jhi; j += 32) {
                acc = fmaf(e, H[j], acc);
                e *= r;
                r *= c32;
            }
        }
        #pragma unroll
        for (int o = 16; o; o >>= 1) acc += __shfl_down_sync(0xffffffffu, acc, o);
        if (lane == 0) S7[wid] = acc;
    }
    __syncthreads();

    if (t == 0) {
        float tot = 0.f;
        #pragma unroll
        for (int k = 0; k < 7; k++) tot += S7[k];
        float inv = 1.0f / fmaxf(tot, 1e-30f);
        float ls = 0.f;
        #pragma unroll
        for (int k = 0; k < 7; k++) {
            float dlt = S7[k] * inv - c_targ[k];
            float aa = fabsf(dlt);
            ls += (aa < 1.f) ? 0.5f * aa * aa : aa - 0.5f;
        }
        g_partial[c * DD + d] = ls;
    }
}

// --------------------------------------------------------------- final ----
// One warp per class; then re-zero counters so the next graph replay starts
// from clean state (statically zero on the very first run).
__global__ void k_final(float* __restrict__ out) {
    int t = threadIdx.x;
    int lane = t & 31, c = t >> 5;            // 19 warps
    __shared__ float sl[NUM_C], sa[NUM_C];
    float s = g_partial[c * DD + lane] + g_partial[c * DD + 32 + lane];
    #pragma unroll
    for (int o = 16; o; o >>= 1) s += __shfl_down_sync(0xffffffffu, s, o);
    if (lane == 0) {
        float act = (g_n[c] >= 1000) ? 1.f : 0.f;
        sl[c] = s * (1.0f / 448.0f) * act;    // mean over 64*7 elements, masked
        sa[c] = act;
    }
    __syncthreads();
    if (t < NUM_C) { g_cnt[t] = 0; g_n[t] = 0; }   // reset for next replay
    if (t == 0) {
        float L = 0.f, A = 0.f;
        #pragma unroll
        for (int cc = 0; cc < NUM_C; cc++) { L += sl[cc]; A += sa[cc]; }
        out[0] = L / A;
    }
}

// -------------------------------------------------------------- launch ----
extern "C" void kernel_launch(void* const* d_in, const int* in_sizes, int n_in,
                              void* d_out, int out_size) {
    const float* feat  = (const float*)d_in[0];
    const int*   label = (const int*)d_in[1];
    // robustness: identify inputs by element count (feature=1048576, label=262144)
    if (n_in >= 2 && in_sizes[0] == 262144) {
        feat  = (const float*)d_in[1];
        label = (const int*)d_in[0];
    }

    k_build<<<64, 256>>>(label);
    dim3 g(DD, NUM_C);
    k_fused<<<g, 256>>>(feat);
    k_final<<<1, NUM_C * 32>>>((float*)d_out);
}

// round 12
// speedup vs baseline: 1.2824x; 1.0110x over previous
#include <cuda_runtime.h>
#include <math.h>

// ---------------------------------------------------------------------------
// HistogramLoss on GB300 — single-pass x-histogram KDE, 3-launch pipeline.
//
// feature: [1, 64, 128, 128] fp32 ; label: [1, 1, 512, 512] int32 ; out: scalar
//
// Per class c, dim d:
//   miu = Σ w x / n,  var = Σ w x²/n - miu² + 1e-10
//   S[k] = Σ_q w[c,q] exp(-12.5 ((miu + k·std - x_q)/std)²),  k = -3..3
//   hist = S/ΣS, targ = const normalized gaussian, loss = mean smooth_l1
//
// Pipeline (counters statically zero; k_final re-zeros them for graph replay):
//   k_build : per-pixel 4x4 label counts -> per-class packed lists via
//             warp-aggregated atomic reservation with PIPELINED atomics
//             (all 19 issued before any result is consumed)
//   k_fused : per (c,d): one pass -> register stats + weighted x-histogram
//             (3072 bins, δ=1/256 over [-6,6)); KDE via on-the-fly gaussian
//             recurrence; smooth-l1 vs hardcoded target
//   k_final : one warp per class, scalar reduce; re-zero counters
// ---------------------------------------------------------------------------

#define NUM_C  19
#define PC     16384            // 128*128 coarse pixels
#define DD     64
#define NBX    3072             // x-histogram bins over [-6, 6), delta = 1/256
#define HWF    1.30f            // gaussian half-window in std units

__device__ unsigned int g_list[NUM_C * PC];   // packed (q<<5)|w
__device__ int    g_cnt[NUM_C];               // entries per class  (zero-init)
__device__ int    g_n[NUM_C];                 // class totals       (zero-init)
__device__ float  g_partial[NUM_C * DD];      // per-(c,d) smooth-l1 sum

// target histogram exp(-0.5 k^2)/sum, k=-3..3 (exact constants)
__constant__ float c_targ[7] = {
    0.00443305f, 0.05400557f, 0.24203623f, 0.39905027f,
    0.24203623f, 0.05400557f, 0.00443305f };

// --------------------------------------------------------------- build ----
// One thread per coarse pixel (128 blocks x 128 threads): count labels in
// its 4x4 fine block, then warp-aggregated reservation with all per-class
// atomics issued back-to-back (pipelined) before any segment is consumed.
__global__ __launch_bounds__(128) void k_build(const int* __restrict__ label) {
    int t = threadIdx.x;
    int lane = t & 31;
    int q = blockIdx.x * 128 + t;           // 128 blocks * 128 = 16384
    int y = q >> 7, x = q & 127;
    const int4* lp = (const int4*)label;    // 512 ints per fine row = 128 int4
    int base = y * 512 + x;                 // int4 index of fine row 4y, col 4x

    int w[NUM_C];
    #pragma unroll
    for (int c = 0; c < NUM_C; c++) w[c] = 0;

    #pragma unroll
    for (int r = 0; r < 4; r++) {
        int4 v = lp[base + r * 128];
        #pragma unroll
        for (int c = 0; c < NUM_C; c++)
            w[c] += (v.x == c) + (v.y == c) + (v.z == c) + (v.w == c);
    }

    // phase 1: ballots + totals for all classes (independent)
    unsigned bal[NUM_C];
    int tot[NUM_C];
    #pragma unroll
    for (int c = 0; c < NUM_C; c++) {
        bal[c] = __ballot_sync(0xffffffffu, w[c] != 0);
        tot[c] = __reduce_add_sync(0xffffffffu, w[c]);
    }

    // phase 2: lane 0 fires ALL segment-reservation atomics back-to-back;
    // the 19 returns overlap in flight instead of serializing.
    int seg[NUM_C];
    if (lane == 0) {
        #pragma unroll
        for (int c = 0; c < NUM_C; c++)
            if (bal[c]) seg[c] = atomicAdd(&g_cnt[c], __popc(bal[c]));
        #pragma unroll
        for (int c = 0; c < NUM_C; c++)
            if (tot[c]) atomicAdd(&g_n[c], tot[c]);   // no return -> REDG
    }

    // phase 3: broadcast segments, scatter entries
    unsigned lmask = (1u << lane) - 1u;
    #pragma unroll
    for (int c = 0; c < NUM_C; c++) {
        int s = __shfl_sync(0xffffffffu, seg[c], 0);
        if (w[c]) g_list[c * PC + s + __popc(bal[c] & lmask)] =
                      ((unsigned)q << 5) | (unsigned)w[c];
    }
}

// --------------------------------------------------------------- fused ----
// One block per (d, c): single pass over the compact list accumulates exact
// register stats AND the weighted x-histogram; then KDE + smooth-l1.
__global__ __launch_bounds__(256) void k_fused(const float* __restrict__ feat) {
    int d = blockIdx.x, c = blockIdx.y;
    int t = threadIdx.x;
    int lane = t & 31, wid = t >> 5;

    __shared__ float H[NBX];
    __shared__ float S7[7];
    __shared__ float r1[8], r2[8];
    __shared__ float s_par[4];     // A, jb0, std_bins, halfwin_bins

    for (int i = t; i < NBX; i += 256) H[i] = 0.f;
    __syncthreads();

    int nnz = g_cnt[c];
    const unsigned int* __restrict__ list = g_list + c * PC;
    const float* __restrict__ xrow = feat + d * PC;

    // ---- single data pass: exact stats + weighted x-histogram ----
    float s1 = 0.f, s2 = 0.f;
    #pragma unroll 8
    for (int i = t; i < nnz; i += 256) {
        unsigned e = list[i];
        float w  = (float)(e & 31u);
        float x  = xrow[e >> 5];
        float wx = w * x;
        s1 += wx;
        s2 = fmaf(wx, x, s2);
        float jf = fmaf(x, 256.f, 1536.f);           // (x+6)*256
        jf = fminf(fmaxf(jf, 0.f), (float)(NBX - 1));
        atomicAdd(&H[(int)jf], w);                   // integer adds: exact
    }
    #pragma unroll
    for (int o = 16; o; o >>= 1) {
        s1 += __shfl_down_sync(0xffffffffu, s1, o);
        s2 += __shfl_down_sync(0xffffffffu, s2, o);
    }
    if (lane == 0) { r1[wid] = s1; r2[wid] = s2; }
    __syncthreads();
    if (t == 0) {
        float a = 0.f, b = 0.f;
        #pragma unroll
        for (int i = 0; i < 8; i++) { a += r1[i]; b += r2[i]; }
        float n   = (float)g_n[c];
        float ns  = fmaxf(n, 1.0f);
        float miu = a / ns;
        float var = b / ns - miu * miu + 1e-10f;
        var = fmaxf(var, 1e-10f);
        float std = sqrtf(var);
        s_par[0] = 12.5f / (var * 65536.0f);          // A (bin units)
        s_par[1] = fmaf(miu, 256.f, 1535.5f);         // jb0: bin coord of miu
        s_par[2] = std * 256.0f;                      // std in bins
        s_par[3] = HWF * std * 256.0f;                // half window in bins
    }
    __syncthreads();

    // ---- 7-bin KDE: warp wid handles k = wid-3 ----
    if (wid < 7) {
        float A  = s_par[0];
        float jb = fmaf((float)(wid - 3), s_par[2], s_par[1]);
        float hw = s_par[3];
        int jlo = max(0,        (int)ceilf(jb - hw));
        int jhi = min(NBX - 1,  (int)floorf(jb + hw));
        float acc = 0.f;
        int j = jlo + lane;
        if (j <= jhi) {
            float dd  = (float)j - jb;
            float e   = __expf(-A * dd * dd);
            float r   = __expf(-A * fmaf(64.f, dd, 1024.f));   // ratio j -> j+32
            float c32 = __expf(-2048.f * A);                   // ratio update
            for (; j <= jhi; j += 32) {
                acc = fmaf(e, H[j], acc);
                e *= r;
                r *= c32;
            }
        }
        #pragma unroll
        for (int o = 16; o; o >>= 1) acc += __shfl_down_sync(0xffffffffu, acc, o);
        if (lane == 0) S7[wid] = acc;
    }
    __syncthreads();

    if (t == 0) {
        float tot = 0.f;
        #pragma unroll
        for (int k = 0; k < 7; k++) tot += S7[k];
        float inv = 1.0f / fmaxf(tot, 1e-30f);
        float ls = 0.f;
        #pragma unroll
        for (int k = 0; k < 7; k++) {
            float dlt = S7[k] * inv - c_targ[k];
            float aa = fabsf(dlt);
            ls += (aa < 1.f) ? 0.5f * aa * aa : aa - 0.5f;
        }
        g_partial[c * DD + d] = ls;
    }
}

// --------------------------------------------------------------- final ----
// One warp per class; then re-zero counters so the next graph replay starts
// from clean state (statically zero on the very first run).
__global__ void k_final(float* __restrict__ out) {
    int t = threadIdx.x;
    int lane = t & 31, c = t >> 5;            // 19 warps
    __shared__ float sl[NUM_C], sa[NUM_C];
    float s = g_partial[c * DD + lane] + g_partial[c * DD + 32 + lane];
    #pragma unroll
    for (int o = 16; o; o >>= 1) s += __shfl_down_sync(0xffffffffu, s, o);
    if (lane == 0) {
        float act = (g_n[c] >= 1000) ? 1.f : 0.f;
        sl[c] = s * (1.0f / 448.0f) * act;    // mean over 64*7 elements, masked
        sa[c] = act;
    }
    __syncthreads();
    if (t < NUM_C) { g_cnt[t] = 0; g_n[t] = 0; }   // reset for next replay
    if (t == 0) {
        float L = 0.f, A = 0.f;
        #pragma unroll
        for (int cc = 0; cc < NUM_C; cc++) { L += sl[cc]; A += sa[cc]; }
        out[0] = L / A;
    }
}

// -------------------------------------------------------------- launch ----
extern "C" void kernel_launch(void* const* d_in, const int* in_sizes, int n_in,
                              void* d_out, int out_size) {
    const float* feat  = (const float*)d_in[0];
    const int*   label = (const int*)d_in[1];
    // robustness: identify inputs by element count (feature=1048576, label=262144)
    if (n_in >= 2 && in_sizes[0] == 262144) {
        feat  = (const float*)d_in[1];
        label = (const int*)d_in[0];
    }

    k_build<<<128, 128>>>(label);
    dim3 g(DD, NUM_C);
    k_fused<<<g, 256>>>(feat);
    k_final<<<1, NUM_C * 32>>>((float*)d_out);
}

// round 13
// speedup vs baseline: 1.5683x; 1.2230x over previous
#include <cuda_runtime.h>
#include <math.h>

// ---------------------------------------------------------------------------
// HistogramLoss on GB300 — single-pass x-histogram KDE, 3-launch pipeline.
//
// feature: [1, 64, 128, 128] fp32 ; label: [1, 1, 512, 512] int32 ; out: scalar
//
// Per class c, dim d:
//   miu = Σ w x / n,  var = Σ w x²/n - miu² + 1e-10
//   S[k] = Σ_q w[c,q] exp(-12.5 ((miu + k·std - x_q)/std)²),  k = -3..3
//   hist = S/ΣS, targ = const normalized gaussian, loss = mean smooth_l1
//
// Pipeline (counters statically zero; k_final re-zeros them for graph replay):
//   k_build : per-pixel 4x4 label counts -> per-class packed lists.
//             Block-aggregated reservation: ONE spread-address atomic
//             instruction per block (19 lanes), 64x less per-address
//             contention than warp-level reservation.
//   k_fused : per (c,d): one pass -> register stats + weighted x-histogram
//             (3072 bins, δ=1/256 over [-6,6)); KDE via on-the-fly gaussian
//             recurrence; smooth-l1 vs hardcoded target
//   k_final : one warp per class, scalar reduce; re-zero counters
// ---------------------------------------------------------------------------

#define NUM_C  19
#define PC     16384            // 128*128 coarse pixels
#define DD     64
#define NBX    3072             // x-histogram bins over [-6, 6), delta = 1/256
#define HWF    1.30f            // gaussian half-window in std units

__device__ unsigned int g_list[NUM_C * PC];   // packed (q<<5)|w
__device__ int    g_cnt[NUM_C];               // entries per class  (zero-init)
__device__ int    g_n[NUM_C];                 // class totals       (zero-init)
__device__ float  g_partial[NUM_C * DD];      // per-(c,d) smooth-l1 sum

// target histogram exp(-0.5 k^2)/sum, k=-3..3 (exact constants)
__constant__ float c_targ[7] = {
    0.00443305f, 0.05400557f, 0.24203623f, 0.39905027f,
    0.24203623f, 0.05400557f, 0.00443305f };

// --------------------------------------------------------------- build ----
// 64 blocks x 256 threads, one thread per coarse pixel.
// Warp ballots -> smem per-warp counts -> warp0 lanes 0..18 do the block's
// single atomic reservation (spread addresses, one ATOMG instruction) and
// the intra-block warp prefix -> every thread scatters its entries.
__global__ __launch_bounds__(256) void k_build(const int* __restrict__ label) {
    __shared__ unsigned short scnt[8][NUM_C];   // per-warp nonzero counts
    __shared__ unsigned short stot[8][NUM_C];   // per-warp weight totals
    __shared__ int   sbase[8][NUM_C];           // intra-block exclusive prefix
    __shared__ int   gbase[NUM_C];              // global segment base

    int t = threadIdx.x;
    int lane = t & 31, wid = t >> 5;
    int q = blockIdx.x * 256 + t;           // 64 blocks * 256 = 16384
    int y = q >> 7, x = q & 127;
    const int4* lp = (const int4*)label;    // 512 ints per fine row = 128 int4
    int base = y * 512 + x;                 // int4 index of fine row 4y, col 4x

    int w[NUM_C];
    #pragma unroll
    for (int c = 0; c < NUM_C; c++) w[c] = 0;

    #pragma unroll
    for (int r = 0; r < 4; r++) {
        int4 v = lp[base + r * 128];
        #pragma unroll
        for (int c = 0; c < NUM_C; c++)
            w[c] += (v.x == c) + (v.y == c) + (v.z == c) + (v.w == c);
    }

    // per-warp ballots + counts into smem
    unsigned bal[NUM_C];
    #pragma unroll
    for (int c = 0; c < NUM_C; c++) {
        bal[c] = __ballot_sync(0xffffffffu, w[c] != 0);
        int tot = __reduce_add_sync(0xffffffffu, w[c]);
        if (lane == 0) {
            scnt[wid][c] = (unsigned short)__popc(bal[c]);
            stot[wid][c] = (unsigned short)tot;
        }
    }
    __syncthreads();

    // warp 0: lane c owns class c — prefix over 8 warps + ONE atomic each
    // (all 19 lanes issue in a single spread-address ATOMG instruction)
    if (wid == 0 && lane < NUM_C) {
        int run = 0, tt = 0;
        #pragma unroll
        for (int ww = 0; ww < 8; ww++) {
            sbase[ww][lane] = run;
            run += scnt[ww][lane];
            tt  += stot[ww][lane];
        }
        gbase[lane] = atomicAdd(&g_cnt[lane], run);
        if (tt) atomicAdd(&g_n[lane], tt);
    }
    __syncthreads();

    // scatter entries
    unsigned lmask = (1u << lane) - 1u;
    #pragma unroll
    for (int c = 0; c < NUM_C; c++) {
        if (w[c]) g_list[c * PC + gbase[c] + sbase[wid][c] + __popc(bal[c] & lmask)] =
                      ((unsigned)q << 5) | (unsigned)w[c];
    }
}

// --------------------------------------------------------------- fused ----
// One block per (d, c): single pass over the compact list accumulates exact
// register stats AND the weighted x-histogram; then KDE + smooth-l1.
__global__ __launch_bounds__(256) void k_fused(const float* __restrict__ feat) {
    int d = blockIdx.x, c = blockIdx.y;
    int t = threadIdx.x;
    int lane = t & 31, wid = t >> 5;

    __shared__ float H[NBX];
    __shared__ float S7[7];
    __shared__ float r1[8], r2[8];
    __shared__ float s_par[4];     // A, jb0, std_bins, halfwin_bins

    for (int i = t; i < NBX; i += 256) H[i] = 0.f;
    __syncthreads();

    int nnz = g_cnt[c];
    const unsigned int* __restrict__ list = g_list + c * PC;
    const float* __restrict__ xrow = feat + d * PC;

    // ---- single data pass: exact stats + weighted x-histogram ----
    float s1 = 0.f, s2 = 0.f;
    #pragma unroll 8
    for (int i = t; i < nnz; i += 256) {
        unsigned e = list[i];
        float w  = (float)(e & 31u);
        float x  = xrow[e >> 5];
        float wx = w * x;
        s1 += wx;
        s2 = fmaf(wx, x, s2);
        float jf = fmaf(x, 256.f, 1536.f);           // (x+6)*256
        jf = fminf(fmaxf(jf, 0.f), (float)(NBX - 1));
        atomicAdd(&H[(int)jf], w);                   // integer adds: exact
    }
    #pragma unroll
    for (int o = 16; o; o >>= 1) {
        s1 += __shfl_down_sync(0xffffffffu, s1, o);
        s2 += __shfl_down_sync(0xffffffffu, s2, o);
    }
    if (lane == 0) { r1[wid] = s1; r2[wid] = s2; }
    __syncthreads();
    if (t == 0) {
        float a = 0.f, b = 0.f;
        #pragma unroll
        for (int i = 0; i < 8; i++) { a += r1[i]; b += r2[i]; }
        float n   = (float)g_n[c];
        float ns  = fmaxf(n, 1.0f);
        float miu = a / ns;
        float var = b / ns - miu * miu + 1e-10f;
        var = fmaxf(var, 1e-10f);
        float std = sqrtf(var);
        s_par[0] = 12.5f / (var * 65536.0f);          // A (bin units)
        s_par[1] = fmaf(miu, 256.f, 1535.5f);         // jb0: bin coord of miu
        s_par[2] = std * 256.0f;                      // std in bins
        s_par[3] = HWF * std * 256.0f;                // half window in bins
    }
    __syncthreads();

    // ---- 7-bin KDE: warp wid handles k = wid-3 ----
    if (wid < 7) {
        float A  = s_par[0];
        float jb = fmaf((float)(wid - 3), s_par[2], s_par[1]);
        float hw = s_par[3];
        int jlo = max(0,        (int)ceilf(jb - hw));
        int jhi = min(NBX - 1,  (int)floorf(jb + hw));
        float acc = 0.f;
        int j = jlo + lane;
        if (j <= jhi) {
            float dd  = (float)j - jb;
            float e   = __expf(-A * dd * dd);
            float r   = __expf(-A * fmaf(64.f, dd, 1024.f));   // ratio j -> j+32
            float c32 = __expf(-2048.f * A);                   // ratio update
            for (; j <= jhi; j += 32) {
                acc = fmaf(e, H[j], acc);
                e *= r;
                r *= c32;
            }
        }
        #pragma unroll
        for (int o = 16; o; o >>= 1) acc += __shfl_down_sync(0xffffffffu, acc, o);
        if (lane == 0) S7[wid] = acc;
    }
    __syncthreads();

    if (t == 0) {
        float tot = 0.f;
        #pragma unroll
        for (int k = 0; k < 7; k++) tot += S7[k];
        float inv = 1.0f / fmaxf(tot, 1e-30f);
        float ls = 0.f;
        #pragma unroll
        for (int k = 0; k < 7; k++) {
            float dlt = S7[k] * inv - c_targ[k];
            float aa = fabsf(dlt);
            ls += (aa < 1.f) ? 0.5f * aa * aa : aa - 0.5f;
        }
        g_partial[c * DD + d] = ls;
    }
}

// --------------------------------------------------------------- final ----
// One warp per class; then re-zero counters so the next graph replay starts
// from clean state (statically zero on the very first run).
__global__ void k_final(float* __restrict__ out) {
    int t = threadIdx.x;
    int lane = t & 31, c = t >> 5;            // 19 warps
    __shared__ float sl[NUM_C], sa[NUM_C];
    float s = g_partial[c * DD + lane] + g_partial[c * DD + 32 + lane];
    #pragma unroll
    for (int o = 16; o; o >>= 1) s += __shfl_down_sync(0xffffffffu, s, o);
    if (lane == 0) {
        float act = (g_n[c] >= 1000) ? 1.f : 0.f;
        sl[c] = s * (1.0f / 448.0f) * act;    // mean over 64*7 elements, masked
        sa[c] = act;
    }
    __syncthreads();
    if (t < NUM_C) { g_cnt[t] = 0; g_n[t] = 0; }   // reset for next replay
    if (t == 0) {
        float L = 0.f, A = 0.f;
        #pragma unroll
        for (int cc = 0; cc < NUM_C; cc++) { L += sl[cc]; A += sa[cc]; }
        out[0] = L / A;
    }
}

// -------------------------------------------------------------- launch ----
extern "C" void kernel_launch(void* const* d_in, const int* in_sizes, int n_in,
                              void* d_out, int out_size) {
    const float* feat  = (const float*)d_in[0];
    const int*   label = (const int*)d_in[1];
    // robustness: identify inputs by element count (feature=1048576, label=262144)
    if (n_in >= 2 && in_sizes[0] == 262144) {
        feat  = (const float*)d_in[1];
        label = (const int*)d_in[0];
    }

    k_build<<<64, 256>>>(label);
    dim3 g(DD, NUM_C);
    k_fused<<<g, 256>>>(feat);
    k_final<<<1, NUM_C * 32>>>((float*)d_out);
}